// round 1
// baseline (speedup 1.0000x reference)
#include <cuda_runtime.h>
#include <cuda_bf16.h>
#include <math.h>

#define NN 50000
#define EE 1600000
#define GG 256
#define HH 128
#define ED 16
#define CSR_CAP (EE + NN)

// ---------------- scratch (static device globals; no allocs) ----------------
__device__ int   g_degcnt[NN];
__device__ int   g_rowptr[NN + 1];
__device__ int   g_wp[NN];
__device__ float g_dis[NN];
__device__ int   g_col[CSR_CAP];
__device__ float g_val[CSR_CAP];
__device__ float g_t [NN * HH];   // GEMM output (pre-aggregation)
__device__ float g_x1[NN * HH];   // ping
__device__ float g_x2[NN * HH];   // pong
__device__ float g_ecolsum[ED];
__device__ float g_meanvec[HH];

// ---------------- init ----------------
__global__ void init_kernel() {
    int i = blockIdx.x * blockDim.x + threadIdx.x;
    if (i < NN) g_degcnt[i] = 1;           // self-loop
    if (blockIdx.x == 0 && threadIdx.x < ED) g_ecolsum[threadIdx.x] = 0.f;
}

// ---------------- degree histogram ----------------
__global__ void degree_kernel(const int* __restrict__ ei) {
    int e = blockIdx.x * blockDim.x + threadIdx.x;
    if (e < EE) atomicAdd(&g_degcnt[ei[EE + e]], 1);   // dst = ei[1][e]
}

// ---------------- single-block exclusive scan + dis + wp ----------------
#define SCAN_T 1024
__global__ __launch_bounds__(SCAN_T) void scan_kernel() {
    __shared__ int sh[SCAN_T];
    const int chunk = (NN + SCAN_T - 1) / SCAN_T;
    int t  = threadIdx.x;
    int lo = t * chunk;
    int hi = min(lo + chunk, NN);
    int sum = 0;
    for (int i = lo; i < hi; i++) sum += g_degcnt[i];
    sh[t] = sum;
    __syncthreads();
    // Hillis-Steele inclusive scan
    for (int off = 1; off < SCAN_T; off <<= 1) {
        int v = (t >= off) ? sh[t - off] : 0;
        __syncthreads();
        sh[t] += v;
        __syncthreads();
    }
    int run = sh[t] - sum;                 // exclusive prefix of this chunk
    for (int i = lo; i < hi; i++) {
        int d = g_degcnt[i];
        g_rowptr[i] = run;
        g_wp[i]     = run;
        g_dis[i]    = rsqrtf((float)d);    // d >= 1 always (self-loop)
        run += d;
    }
    if (t == SCAN_T - 1) g_rowptr[NN] = sh[SCAN_T - 1];
}

// ---------------- CSR fill ----------------
__global__ void csr_fill_edges(const int* __restrict__ ei) {
    int e = blockIdx.x * blockDim.x + threadIdx.x;
    if (e >= EE) return;
    int s = ei[e];
    int d = ei[EE + e];
    int pos = atomicAdd(&g_wp[d], 1);
    g_col[pos] = s;
    g_val[pos] = g_dis[s] * g_dis[d];
}

__global__ void csr_fill_loops() {
    int i = blockIdx.x * blockDim.x + threadIdx.x;
    if (i >= NN) return;
    int pos = atomicAdd(&g_wp[i], 1);
    float d = g_dis[i];
    g_col[pos] = i;
    g_val[pos] = d * d;
}

// ---------------- edge_attr column sums ----------------
__global__ __launch_bounds__(256) void edge_colsum_kernel(const float* __restrict__ ea) {
    __shared__ float sh[ED];
    if (threadIdx.x < ED) sh[threadIdx.x] = 0.f;
    __syncthreads();
    const long long total = (long long)EE * ED;
    long long idx = (long long)blockIdx.x * blockDim.x + threadIdx.x;
    const long long stride = (long long)gridDim.x * blockDim.x;   // multiple of 16
    int c = (int)(idx & (ED - 1));
    float s = 0.f;
    for (; idx < total; idx += stride) s += ea[idx];
    atomicAdd(&sh[c], s);
    __syncthreads();
    if (threadIdx.x < ED) atomicAdd(&g_ecolsum[threadIdx.x], sh[threadIdx.x]);
}

// meanvec[h] = eb[h] + sum_k (ecolsum[k]/E) * eW[k][h]
__global__ void meanvec_kernel(const float* __restrict__ eW, const float* __restrict__ eb) {
    int h = threadIdx.x;
    const float inv = 1.0f / (float)EE;
    float m = eb[h];
    #pragma unroll
    for (int k = 0; k < ED; k++) m += (g_ecolsum[k] * inv) * eW[k * HH + h];
    g_meanvec[h] = m;
}

// ---------------- SGEMM 128x128 tile, K-step 8, 256 threads, 8x8 per thread ----------------
__global__ __launch_bounds__(256) void sgemm_kernel(const float* __restrict__ A,
                                                    const float* __restrict__ B,
                                                    float* __restrict__ C, int M) {
    __shared__ float As[8][128];
    __shared__ float Bs[8][128];
    const int tid  = threadIdx.x;
    const int row0 = blockIdx.x * 128;
    const int ar = tid >> 1, ac = (tid & 1) * 4;     // A tile: 128 rows x 8 k
    const int br = tid >> 5, bc = (tid & 31) * 4;    // B tile: 8 k x 128 cols
    const int ty = tid >> 4, tx = tid & 15;

    float acc[8][8];
    #pragma unroll
    for (int m = 0; m < 8; m++)
        #pragma unroll
        for (int n = 0; n < 8; n++) acc[m][n] = 0.f;

    for (int k0 = 0; k0 < 128; k0 += 8) {
        int gr = row0 + ar;
        float4 av = (gr < M) ? *(const float4*)&A[(size_t)gr * 128 + k0 + ac]
                             : make_float4(0.f, 0.f, 0.f, 0.f);
        As[ac + 0][ar] = av.x;
        As[ac + 1][ar] = av.y;
        As[ac + 2][ar] = av.z;
        As[ac + 3][ar] = av.w;
        *(float4*)&Bs[br][bc] = *(const float4*)&B[(size_t)(k0 + br) * 128 + bc];
        __syncthreads();
        #pragma unroll
        for (int k = 0; k < 8; k++) {
            float a[8], b[8];
            #pragma unroll
            for (int m = 0; m < 8; m++) a[m] = As[k][ty * 8 + m];
            #pragma unroll
            for (int n = 0; n < 8; n++) b[n] = Bs[k][tx * 8 + n];
            #pragma unroll
            for (int m = 0; m < 8; m++)
                #pragma unroll
                for (int n = 0; n < 8; n++) acc[m][n] = fmaf(a[m], b[n], acc[m][n]);
        }
        __syncthreads();
    }
    #pragma unroll
    for (int m = 0; m < 8; m++) {
        int row = row0 + ty * 8 + m;
        if (row < M) {
            *(float4*)&C[(size_t)row * 128 + tx * 8]     = make_float4(acc[m][0], acc[m][1], acc[m][2], acc[m][3]);
            *(float4*)&C[(size_t)row * 128 + tx * 8 + 4] = make_float4(acc[m][4], acc[m][5], acc[m][6], acc[m][7]);
        }
    }
}

// ---------------- aggregation: warp per node, CSR gather, relu(acc+b)(+meanvec) ----------------
__global__ __launch_bounds__(256) void agg_kernel(const float* __restrict__ t,
                                                  const float* __restrict__ bias,
                                                  float* __restrict__ out,
                                                  int addmean) {
    int warp = (blockIdx.x * blockDim.x + threadIdx.x) >> 5;
    int lane = threadIdx.x & 31;
    if (warp >= NN) return;
    int s = g_rowptr[warp];
    int e = g_rowptr[warp + 1];
    float4 acc  = make_float4(0.f, 0.f, 0.f, 0.f);
    float4 acc2 = make_float4(0.f, 0.f, 0.f, 0.f);
    int p = s;
    for (; p + 1 < e; p += 2) {
        int   c0 = g_col[p];     float w0 = g_val[p];
        int   c1 = g_col[p + 1]; float w1 = g_val[p + 1];
        float4 v0 = *(const float4*)(t + (size_t)c0 * 128 + lane * 4);
        float4 v1 = *(const float4*)(t + (size_t)c1 * 128 + lane * 4);
        acc.x  = fmaf(v0.x, w0, acc.x);  acc.y  = fmaf(v0.y, w0, acc.y);
        acc.z  = fmaf(v0.z, w0, acc.z);  acc.w  = fmaf(v0.w, w0, acc.w);
        acc2.x = fmaf(v1.x, w1, acc2.x); acc2.y = fmaf(v1.y, w1, acc2.y);
        acc2.z = fmaf(v1.z, w1, acc2.z); acc2.w = fmaf(v1.w, w1, acc2.w);
    }
    if (p < e) {
        int c0 = g_col[p]; float w0 = g_val[p];
        float4 v0 = *(const float4*)(t + (size_t)c0 * 128 + lane * 4);
        acc.x = fmaf(v0.x, w0, acc.x); acc.y = fmaf(v0.y, w0, acc.y);
        acc.z = fmaf(v0.z, w0, acc.z); acc.w = fmaf(v0.w, w0, acc.w);
    }
    acc.x += acc2.x; acc.y += acc2.y; acc.z += acc2.z; acc.w += acc2.w;
    float4 bb = *(const float4*)(bias + lane * 4);
    acc.x = fmaxf(acc.x + bb.x, 0.f);
    acc.y = fmaxf(acc.y + bb.y, 0.f);
    acc.z = fmaxf(acc.z + bb.z, 0.f);
    acc.w = fmaxf(acc.w + bb.w, 0.f);
    if (addmean) {
        float4 mv = *(const float4*)(g_meanvec + lane * 4);
        acc.x += mv.x; acc.y += mv.y; acc.z += mv.z; acc.w += mv.w;
    }
    *(float4*)(out + (size_t)warp * 128 + lane * 4) = acc;
}

// ---------------- fused pooling (max+mean per graph) + MLP ----------------
__global__ __launch_bounds__(128) void pool_mlp_kernel(const float* __restrict__ x,
                                                       const int* __restrict__ batch,
                                                       const float* __restrict__ l1W,
                                                       const float* __restrict__ l1b,
                                                       const float* __restrict__ l2W,
                                                       const float* __restrict__ l2b,
                                                       float* __restrict__ out) {
    int g = blockIdx.x;
    int d = threadIdx.x;   // 0..127
    // binary searches (batch is sorted ascending)
    int lo = 0, hi = NN;
    while (lo < hi) { int mid = (lo + hi) >> 1; if (batch[mid] < g) lo = mid + 1; else hi = mid; }
    int start = lo;
    hi = NN;
    while (lo < hi) { int mid = (lo + hi) >> 1; if (batch[mid] < g + 1) lo = mid + 1; else hi = mid; }
    int end = lo;

    float mx = -3.402823466e38f, sm = 0.f;
    for (int i = start; i < end; i++) {
        float v = x[(size_t)i * 128 + d];
        mx = fmaxf(mx, v);
        sm += v;
    }
    __shared__ float pooled[256];
    __shared__ float hid[64];
    pooled[d]       = mx;
    pooled[128 + d] = sm / (float)(end - start);
    __syncthreads();
    if (d < 64) {
        float h = l1b[d];
        #pragma unroll 8
        for (int k = 0; k < 256; k++) h = fmaf(pooled[k], l1W[k * 64 + d], h);
        hid[d] = fmaxf(h, 0.f);
    }
    __syncthreads();
    if (d == 0) {
        float s = l2b[0];
        #pragma unroll 8
        for (int k = 0; k < 64; k++) s = fmaf(hid[k], l2W[k], s);
        out[g] = s;
    }
}

// ---------------- launch ----------------
extern "C" void kernel_launch(void* const* d_in, const int* in_sizes, int n_in,
                              void* d_out, int out_size) {
    const float* x    = (const float*)d_in[0];
    const int*   ei   = (const int*)  d_in[1];
    const float* ea   = (const float*)d_in[2];
    const int*   bat  = (const int*)  d_in[3];
    const float* W0   = (const float*)d_in[4];
    const float* b0   = (const float*)d_in[5];
    const float* W1   = (const float*)d_in[6];
    const float* b1   = (const float*)d_in[7];
    const float* W2   = (const float*)d_in[8];
    const float* b2   = (const float*)d_in[9];
    const float* eW   = (const float*)d_in[10];
    const float* eb   = (const float*)d_in[11];
    const float* l1W  = (const float*)d_in[12];
    const float* l1b  = (const float*)d_in[13];
    const float* l2W  = (const float*)d_in[14];
    const float* l2b  = (const float*)d_in[15];
    float* out = (float*)d_out;

    float *t, *x1, *x2;
    cudaGetSymbolAddress((void**)&t,  g_t);
    cudaGetSymbolAddress((void**)&x1, g_x1);
    cudaGetSymbolAddress((void**)&x2, g_x2);

    const int TB = 256;
    // graph preprocessing
    init_kernel<<<(NN + TB - 1) / TB, TB>>>();
    degree_kernel<<<(EE + TB - 1) / TB, TB>>>(ei);
    scan_kernel<<<1, SCAN_T>>>();
    csr_fill_edges<<<(EE + TB - 1) / TB, TB>>>(ei);
    csr_fill_loops<<<(NN + TB - 1) / TB, TB>>>();
    // edge-feature mean (linearity: mean(ea@eW+eb) = mean(ea)@eW+eb)
    edge_colsum_kernel<<<512, TB>>>(ea);
    meanvec_kernel<<<1, HH>>>(eW, eb);

    const int gemm_grid = (NN + 127) / 128;
    const int agg_grid  = (NN * 32 + TB - 1) / TB;   // warp per node
    // layer 0
    sgemm_kernel<<<gemm_grid, TB>>>(x, W0, t, NN);
    agg_kernel<<<agg_grid, TB>>>(t, b0, x1, 0);
    // layer 1
    sgemm_kernel<<<gemm_grid, TB>>>(x1, W1, t, NN);
    agg_kernel<<<agg_grid, TB>>>(t, b1, x2, 0);
    // layer 2 (+ broadcast edge-feature mean)
    sgemm_kernel<<<gemm_grid, TB>>>(x2, W2, t, NN);
    agg_kernel<<<agg_grid, TB>>>(t, b2, x1, 1);
    // pooling + MLP
    pool_mlp_kernel<<<GG, HH>>>(x1, bat, l1W, l1b, l2W, l2b, out);
}

// round 4
// speedup vs baseline: 1.1708x; 1.1708x over previous
#include <cuda_runtime.h>
#include <cuda_fp16.h>
#include <math.h>

#define NN 50000
#define EE 1600000
#define GG 256
#define HH 128
#define ED 16

// ---------------- scratch (static device globals; no allocs) ----------------
__device__ int    g_degcnt[NN];       // deg including self-loop
__device__ int    g_rowptr[NN + 1];   // edge-only CSR offsets
__device__ int    g_wp[NN];
__device__ float  g_dis[NN];
__device__ int    g_col[EE];
__device__ __half g_t[NN * HH];       // dis-prescaled GEMM output (fp16)
__device__ float  g_x1[NN * HH];      // ping
__device__ float  g_x2[NN * HH];      // pong
__device__ float  g_ecolsum[ED];
__device__ float  g_meanvec[HH];

// ---------------- init ----------------
__global__ void init_kernel() {
    int i = blockIdx.x * blockDim.x + threadIdx.x;
    if (i < NN) g_degcnt[i] = 1;           // self-loop
    if (blockIdx.x == 0 && threadIdx.x < ED) g_ecolsum[threadIdx.x] = 0.f;
}

// ---------------- degree histogram ----------------
__global__ void degree_kernel(const int* __restrict__ ei) {
    int e = blockIdx.x * blockDim.x + threadIdx.x;
    if (e < EE) atomicAdd(&g_degcnt[ei[EE + e]], 1);   // dst = ei[1][e]
}

// ---------------- single-block exclusive scan (edge-only) + dis + wp ----------------
#define SCAN_T 1024
__global__ __launch_bounds__(SCAN_T) void scan_kernel() {
    __shared__ int sh[SCAN_T];
    const int chunk = (NN + SCAN_T - 1) / SCAN_T;
    int t  = threadIdx.x;
    int lo = t * chunk;
    int hi = min(lo + chunk, NN);
    int sum = 0;
    for (int i = lo; i < hi; i++) sum += g_degcnt[i] - 1;   // edges only
    sh[t] = sum;
    __syncthreads();
    for (int off = 1; off < SCAN_T; off <<= 1) {
        int v = (t >= off) ? sh[t - off] : 0;
        __syncthreads();
        sh[t] += v;
        __syncthreads();
    }
    int run = sh[t] - sum;
    for (int i = lo; i < hi; i++) {
        int d = g_degcnt[i];
        g_rowptr[i] = run;
        g_wp[i]     = run;
        g_dis[i]    = rsqrtf((float)d);    // deg includes self-loop, >= 1
        run += d - 1;
    }
    if (t == SCAN_T - 1) g_rowptr[NN] = sh[SCAN_T - 1];
}

// ---------------- CSR fill (col only; weights folded into epilogue/agg) ----------------
__global__ void csr_fill_edges(const int* __restrict__ ei) {
    int e = blockIdx.x * blockDim.x + threadIdx.x;
    if (e >= EE) return;
    int s = ei[e];
    int d = ei[EE + e];
    int pos = atomicAdd(&g_wp[d], 1);
    g_col[pos] = s;
}

// ---------------- edge_attr column sums ----------------
__global__ __launch_bounds__(256) void edge_colsum_kernel(const float* __restrict__ ea) {
    __shared__ float sh[ED];
    if (threadIdx.x < ED) sh[threadIdx.x] = 0.f;
    __syncthreads();
    const long long total = (long long)EE * ED;
    long long idx = (long long)blockIdx.x * blockDim.x + threadIdx.x;
    const long long stride = (long long)gridDim.x * blockDim.x;   // multiple of 16
    int c = (int)(idx & (ED - 1));
    float s = 0.f;
    for (; idx < total; idx += stride) s += ea[idx];
    atomicAdd(&sh[c], s);
    __syncthreads();
    if (threadIdx.x < ED) atomicAdd(&g_ecolsum[threadIdx.x], sh[threadIdx.x]);
}

__global__ void meanvec_kernel(const float* __restrict__ eW, const float* __restrict__ eb) {
    int h = threadIdx.x;
    const float inv = 1.0f / (float)EE;
    float m = eb[h];
    #pragma unroll
    for (int k = 0; k < ED; k++) m += (g_ecolsum[k] * inv) * eW[k * HH + h];
    g_meanvec[h] = m;
}

// ---------------- SGEMM 128x128 tile; epilogue scales by dis[row], stores fp16 ----------------
__global__ __launch_bounds__(256) void sgemm_kernel(const float* __restrict__ A,
                                                    const float* __restrict__ B,
                                                    __half* __restrict__ C, int M) {
    __shared__ float As[8][128];
    __shared__ float Bs[8][128];
    const int tid  = threadIdx.x;
    const int row0 = blockIdx.x * 128;
    const int ar = tid >> 1, ac = (tid & 1) * 4;
    const int br = tid >> 5, bc = (tid & 31) * 4;
    const int ty = tid >> 4, tx = tid & 15;

    float acc[8][8];
    #pragma unroll
    for (int m = 0; m < 8; m++)
        #pragma unroll
        for (int n = 0; n < 8; n++) acc[m][n] = 0.f;

    for (int k0 = 0; k0 < 128; k0 += 8) {
        int gr = row0 + ar;
        float4 av = (gr < M) ? *(const float4*)&A[(size_t)gr * 128 + k0 + ac]
                             : make_float4(0.f, 0.f, 0.f, 0.f);
        As[ac + 0][ar] = av.x;
        As[ac + 1][ar] = av.y;
        As[ac + 2][ar] = av.z;
        As[ac + 3][ar] = av.w;
        *(float4*)&Bs[br][bc] = *(const float4*)&B[(size_t)(k0 + br) * 128 + bc];
        __syncthreads();
        #pragma unroll
        for (int k = 0; k < 8; k++) {
            float a[8], b[8];
            #pragma unroll
            for (int m = 0; m < 8; m++) a[m] = As[k][ty * 8 + m];
            #pragma unroll
            for (int n = 0; n < 8; n++) b[n] = Bs[k][tx * 8 + n];
            #pragma unroll
            for (int m = 0; m < 8; m++)
                #pragma unroll
                for (int n = 0; n < 8; n++) acc[m][n] = fmaf(a[m], b[n], acc[m][n]);
        }
        __syncthreads();
    }
    #pragma unroll
    for (int m = 0; m < 8; m++) {
        int row = row0 + ty * 8 + m;
        if (row < M) {
            float s = g_dis[row];
            // 16-byte ALIGNED staging (uint4 punning of a 4-byte-aligned array is a trap)
            __align__(16) __half2 h[4];
            #pragma unroll
            for (int q = 0; q < 4; q++)
                h[q] = __floats2half2_rn(acc[m][2 * q] * s, acc[m][2 * q + 1] * s);
            *(uint4*)&C[(size_t)row * 128 + tx * 8] = *(const uint4*)h;
        }
    }
}

// ---------------- aggregation: warp/node, fp16 gather, implicit self-loop ----------------
__global__ __launch_bounds__(256) void agg_kernel(const __half* __restrict__ t,
                                                  const float* __restrict__ bias,
                                                  float* __restrict__ out,
                                                  int addmean) {
    int warp = (blockIdx.x * blockDim.x + threadIdx.x) >> 5;
    int lane = threadIdx.x & 31;
    if (warp >= NN) return;
    int s = g_rowptr[warp];
    int e = g_rowptr[warp + 1];

    // self-loop: t' row of this node (weight 1; dis^2 comes from prescale + postscale)
    uint2 raw = *(const uint2*)(t + (size_t)warp * 128 + lane * 4);
    float2 p0 = __half22float2(*(const __half2*)&raw.x);
    float2 p1 = __half22float2(*(const __half2*)&raw.y);
    float4 acc  = make_float4(p0.x, p0.y, p1.x, p1.y);
    float4 acc2 = make_float4(0.f, 0.f, 0.f, 0.f);

    int p = s;
    for (; p + 1 < e; p += 2) {
        int c0 = g_col[p];
        int c1 = g_col[p + 1];
        uint2 r0 = *(const uint2*)(t + (size_t)c0 * 128 + lane * 4);
        uint2 r1 = *(const uint2*)(t + (size_t)c1 * 128 + lane * 4);
        float2 a0 = __half22float2(*(const __half2*)&r0.x);
        float2 a1 = __half22float2(*(const __half2*)&r0.y);
        float2 b0 = __half22float2(*(const __half2*)&r1.x);
        float2 b1 = __half22float2(*(const __half2*)&r1.y);
        acc.x  += a0.x; acc.y  += a0.y; acc.z  += a1.x; acc.w  += a1.y;
        acc2.x += b0.x; acc2.y += b0.y; acc2.z += b1.x; acc2.w += b1.y;
    }
    if (p < e) {
        int c0 = g_col[p];
        uint2 r0 = *(const uint2*)(t + (size_t)c0 * 128 + lane * 4);
        float2 a0 = __half22float2(*(const __half2*)&r0.x);
        float2 a1 = __half22float2(*(const __half2*)&r0.y);
        acc.x += a0.x; acc.y += a0.y; acc.z += a1.x; acc.w += a1.y;
    }
    acc.x += acc2.x; acc.y += acc2.y; acc.z += acc2.z; acc.w += acc2.w;

    float disd = g_dis[warp];
    float4 bb = *(const float4*)(bias + lane * 4);
    acc.x = fmaxf(fmaf(acc.x, disd, bb.x), 0.f);
    acc.y = fmaxf(fmaf(acc.y, disd, bb.y), 0.f);
    acc.z = fmaxf(fmaf(acc.z, disd, bb.z), 0.f);
    acc.w = fmaxf(fmaf(acc.w, disd, bb.w), 0.f);
    if (addmean) {
        float4 mv = *(const float4*)(g_meanvec + lane * 4);
        acc.x += mv.x; acc.y += mv.y; acc.z += mv.z; acc.w += mv.w;
    }
    *(float4*)(out + (size_t)warp * 128 + lane * 4) = acc;
}

// ---------------- fused pooling (max+mean per graph) + MLP ----------------
__global__ __launch_bounds__(128) void pool_mlp_kernel(const float* __restrict__ x,
                                                       const int* __restrict__ batch,
                                                       const float* __restrict__ l1W,
                                                       const float* __restrict__ l1b,
                                                       const float* __restrict__ l2W,
                                                       const float* __restrict__ l2b,
                                                       float* __restrict__ out) {
    int g = blockIdx.x;
    int d = threadIdx.x;   // 0..127
    int lo = 0, hi = NN;
    while (lo < hi) { int mid = (lo + hi) >> 1; if (batch[mid] < g) lo = mid + 1; else hi = mid; }
    int start = lo;
    hi = NN;
    while (lo < hi) { int mid = (lo + hi) >> 1; if (batch[mid] < g + 1) lo = mid + 1; else hi = mid; }
    int end = lo;

    float mx = -3.402823466e38f, sm = 0.f;
    for (int i = start; i < end; i++) {
        float v = x[(size_t)i * 128 + d];
        mx = fmaxf(mx, v);
        sm += v;
    }
    __shared__ float pooled[256];
    __shared__ float hid[64];
    pooled[d]       = mx;
    pooled[128 + d] = sm / (float)(end - start);
    __syncthreads();
    if (d < 64) {
        float h = l1b[d];
        #pragma unroll 8
        for (int k = 0; k < 256; k++) h = fmaf(pooled[k], l1W[k * 64 + d], h);
        hid[d] = fmaxf(h, 0.f);
    }
    __syncthreads();
    if (d == 0) {
        float s = l2b[0];
        #pragma unroll 8
        for (int k = 0; k < 64; k++) s = fmaf(hid[k], l2W[k], s);
        out[g] = s;
    }
}

// ---------------- launch ----------------
extern "C" void kernel_launch(void* const* d_in, const int* in_sizes, int n_in,
                              void* d_out, int out_size) {
    const float* x    = (const float*)d_in[0];
    const int*   ei   = (const int*)  d_in[1];
    const float* ea   = (const float*)d_in[2];
    const int*   bat  = (const int*)  d_in[3];
    const float* W0   = (const float*)d_in[4];
    const float* b0   = (const float*)d_in[5];
    const float* W1   = (const float*)d_in[6];
    const float* b1   = (const float*)d_in[7];
    const float* W2   = (const float*)d_in[8];
    const float* b2   = (const float*)d_in[9];
    const float* eW   = (const float*)d_in[10];
    const float* eb   = (const float*)d_in[11];
    const float* l1W  = (const float*)d_in[12];
    const float* l1b  = (const float*)d_in[13];
    const float* l2W  = (const float*)d_in[14];
    const float* l2b  = (const float*)d_in[15];
    float* out = (float*)d_out;

    __half *t;
    float *x1, *x2;
    cudaGetSymbolAddress((void**)&t,  g_t);
    cudaGetSymbolAddress((void**)&x1, g_x1);
    cudaGetSymbolAddress((void**)&x2, g_x2);

    const int TB = 256;
    init_kernel<<<(NN + TB - 1) / TB, TB>>>();
    degree_kernel<<<(EE + TB - 1) / TB, TB>>>(ei);
    scan_kernel<<<1, SCAN_T>>>();
    csr_fill_edges<<<(EE + TB - 1) / TB, TB>>>(ei);
    edge_colsum_kernel<<<1024, TB>>>(ea);
    meanvec_kernel<<<1, HH>>>(eW, eb);

    const int gemm_grid = (NN + 127) / 128;
    const int agg_grid  = (NN * 32 + TB - 1) / TB;
    // layer 0
    sgemm_kernel<<<gemm_grid, TB>>>(x, W0, t, NN);
    agg_kernel<<<agg_grid, TB>>>(t, b0, x1, 0);
    // layer 1
    sgemm_kernel<<<gemm_grid, TB>>>(x1, W1, t, NN);
    agg_kernel<<<agg_grid, TB>>>(t, b1, x2, 0);
    // layer 2 (+ broadcast edge-feature mean)
    sgemm_kernel<<<gemm_grid, TB>>>(x2, W2, t, NN);
    agg_kernel<<<agg_grid, TB>>>(t, b2, x1, 1);
    // pooling + MLP
    pool_mlp_kernel<<<GG, HH>>>(x1, bat, l1W, l1b, l2W, l2b, out);
}